// round 5
// baseline (speedup 1.0000x reference)
#include <cuda_runtime.h>
#include <cstdint>
#include <math.h>

#define NUMB   4
#define PRE    1024
#define CAND   4096
#define HBINS  65536
#define MAXN   200000
#define TOPK   2048

// ---------------- device scratch (static, no runtime alloc) ----------------
__device__ unsigned long long g_keyarr[MAXN];
__device__ unsigned           g_hist[NUMB][HBINS];
__device__ unsigned           g_thr[NUMB];
__device__ int                g_ccnt[NUMB];
__device__ unsigned long long g_cand[NUMB][CAND];
__device__ unsigned long long g_prec[NUMB][CAND];
__device__ unsigned long long g_sel[NUMB][PRE];
__device__ float              g_boxes[NUMB][PRE][8];
__device__ unsigned           g_mask[NUMB][PRE][32];
__device__ unsigned           g_rowflag[NUMB][32];

__device__ __forceinline__ float exp_cr(float x)  { return (float)exp((double)x); }
__device__ __forceinline__ float atan2_cr(float y, float x) {
    return (float)atan2((double)y, (double)x);
}

// ---------------- K0: zero hist / cand / counters / flags ----------------
__global__ void k_init() {
    int i = blockIdx.x * 256 + threadIdx.x;           // grid covers 262144
    ((unsigned*)g_hist)[i] = 0;                        // NUMB*HBINS == 262144
    if (i < NUMB * CAND * 2) ((unsigned*)g_cand)[i] = 0;
    if (i < NUMB) { g_ccnt[i] = 0; }
    if (i < NUMB * 32) ((unsigned*)g_rowflag)[i] = 0;
}

// ---------------- K1: APPROX score pass + histogram ----------------------
// warp-per-point: lane k covers feature rows [k*8, k*8+8)
__global__ void __launch_bounds__(256) k_score(
        const float* __restrict__ feat,
        const int*   __restrict__ bidx,
        const float* __restrict__ Wc,
        const float* __restrict__ bc,
        const float* __restrict__ Wr,
        const float* __restrict__ br,
        int N) {
    const int warp = threadIdx.x >> 5;
    const int lane = threadIdx.x & 31;

    float wd[8], w8[8];
#pragma unroll
    for (int c = 0; c < 8; c++) {
        int row = lane * 8 + c;
        wd[c] = Wc[row * 2 + 1] - Wc[row * 2 + 0];
        w8[c] = Wr[row * 9 + 8];
    }
    const float bd  = bc[1] - bc[0];
    const float b8r = br[8];

    const int tile0 = blockIdx.x * 256;

    for (int i = 0; i < 32; i++) {
        int p = tile0 + warp * 32 + i;
        float accd = 0.0f, accr = 0.0f;
        if (p < N) {
            const float4* f4 = (const float4*)(feat + (size_t)p * 256);
            float4 a = f4[lane * 2 + 0];
            float4 b = f4[lane * 2 + 1];
            accd = a.x * wd[0] + a.y * wd[1] + a.z * wd[2] + a.w * wd[3]
                 + b.x * wd[4] + b.y * wd[5] + b.z * wd[6] + b.w * wd[7];
            accr = a.x * w8[0] + a.y * w8[1] + a.z * w8[2] + a.w * w8[3]
                 + b.x * w8[4] + b.y * w8[5] + b.z * w8[6] + b.w * w8[7];
        }
#pragma unroll
        for (int o = 16; o > 0; o >>= 1) {
            accd += __shfl_xor_sync(0xffffffffu, accd, o);
            accr += __shfl_xor_sync(0xffffffffu, accr, o);
        }
        if (lane == 0 && p < N) {
            float s = 1.0f / ((1.0f + expf(-(accd + bd))) * (1.0f + expf(-(accr + b8r))));
            unsigned sb = __float_as_uint(s);
            g_keyarr[p] = ((unsigned long long)sb << 32) | (unsigned)(~(unsigned)p);
            atomicAdd(&g_hist[bidx[p]][sb >> 16], 1u);
        }
    }
}

// ---------------- K2: per-batch threshold from histogram ------------------
__global__ void k_thresh() {
    const int b = blockIdx.x;
    const int t = threadIdx.x;
    __shared__ int sm[1024];
    const unsigned* h = g_hist[b];
    const int base = t * 64;

    int s = 0;
#pragma unroll 8
    for (int i = 0; i < 64; i++) s += (int)h[base + i];
    sm[t] = s;
    __syncthreads();
    for (int off = 1; off < 1024; off <<= 1) {
        int v = (t + off < 1024) ? sm[t + off] : 0;
        __syncthreads();
        sm[t] += v;
        __syncthreads();
    }

    if (sm[0] < TOPK) {
        if (t == 0) g_thr[b] = 0u;
        return;
    }
    bool found = (sm[t] >= TOPK) && (t == 1023 || sm[t + 1] < TOPK);
    if (found) {
        int acc = (t < 1023) ? sm[t + 1] : 0;
        int B = base;
        for (int i = 63; i >= 0; i--) {
            acc += (int)h[base + i];
            if (acc >= TOPK) { B = base + i; break; }
        }
        g_thr[b] = ((unsigned)B) << 16;
    }
}

// ---------------- K3: compact candidates >= threshold ---------------------
__global__ void k_compact(const int* __restrict__ bidx, int N) {
    int p = blockIdx.x * 256 + threadIdx.x;
    if (p >= N) return;
    unsigned long long key = g_keyarr[p];
    int b = bidx[p];
    if ((unsigned)(key >> 32) >= g_thr[b]) {
        int slot = atomicAdd(&g_ccnt[b], 1);
        if (slot < CAND) g_cand[b][slot] = key;
    }
}

// ---------------- K4: PRECISE rescore of candidates -----------------------
// warp per candidate; compensated f32 (TwoProd+TwoSum) per lane, combined
// and reduced in double -> essentially the exact score, rounded to f32.
__global__ void __launch_bounds__(128) k_rescore(
        const float* __restrict__ feat,
        const float* __restrict__ Wc,
        const float* __restrict__ bc,
        const float* __restrict__ Wr,
        const float* __restrict__ br,
        int N) {
    __shared__ float swc0[256], swc1[256], sw8[256];
    for (int i = threadIdx.x; i < 256; i += 128) {
        swc0[i] = Wc[2 * i + 0];
        swc1[i] = Wc[2 * i + 1];
        sw8[i]  = Wr[9 * i + 8];
    }
    __syncthreads();

    const int b = blockIdx.y;
    const int warp = threadIdx.x >> 5;
    const int lane = threadIdx.x & 31;
    const int k = blockIdx.x * 4 + warp;

    unsigned long long key = g_cand[b][k];
    unsigned idx = ~(unsigned)(key & 0xffffffffu);
    bool valid = (idx < (unsigned)N);

    double d0 = 0.0, d1 = 0.0, d2 = 0.0;
    if (valid) {
        const float4* f4 = (const float4*)(feat + (size_t)idx * 256);
        float4 a  = f4[lane * 2 + 0];
        float4 c4 = f4[lane * 2 + 1];
        float fv[8] = {a.x, a.y, a.z, a.w, c4.x, c4.y, c4.z, c4.w};
        const float* wp[3] = {&swc0[lane * 8], &swc1[lane * 8], &sw8[lane * 8]};
        double* dp[3] = {&d0, &d1, &d2};
#pragma unroll
        for (int o = 0; o < 3; o++) {
            float s = 0.0f, comp = 0.0f;
#pragma unroll
            for (int c = 0; c < 8; c++) {
                float v = fv[c], w = wp[o][c];
                float p = __fmul_rn(v, w);
                float e = __fmaf_rn(v, w, -p);      // exact product tail
                float t = __fadd_rn(s, p);          // Knuth TwoSum
                float bv = __fadd_rn(t, -s);
                float c1 = __fadd_rn(s, -__fadd_rn(t, -bv));
                float c2 = __fadd_rn(p, -bv);
                comp = __fadd_rn(comp, __fadd_rn(c1, c2));
                comp = __fadd_rn(comp, e);
                s = t;
            }
            *dp[o] = (double)s + (double)comp;
        }
    }
#pragma unroll
    for (int o = 16; o > 0; o >>= 1) {
        d0 += __shfl_xor_sync(0xffffffffu, d0, o);
        d1 += __shfl_xor_sync(0xffffffffu, d1, o);
        d2 += __shfl_xor_sync(0xffffffffu, d2, o);
    }

    if (lane == 0) {
        unsigned long long outk = 0ull;
        if (valid) {
            double l0 = d0 + (double)bc[0];
            double l1 = d1 + (double)bc[1];
            double r8 = d2 + (double)br[8];
            double m  = fmax(l0, l1);
            double e0 = exp(l0 - m);
            double e1 = exp(l1 - m);
            double conf = e1 / (e0 + e1);
            double scr  = 1.0 / (1.0 + exp(-r8));
            float sf = (float)(conf * scr);
            outk = ((unsigned long long)__float_as_uint(sf) << 32) |
                   (unsigned)(key & 0xffffffffu);
        }
        g_prec[b][k] = outk;
    }
}

// ---------------- K5: re-rank 4096 precise keys -> top 1024 ---------------
__global__ void k_rank() {
    const int b = blockIdx.x;
    const int t = threadIdx.x;
    __shared__ unsigned long long s[CAND];
#pragma unroll
    for (int rr = 0; rr < 4; rr++) s[t + rr * 1024] = g_prec[b][t + rr * 1024];

    for (unsigned k = 2; k <= CAND; k <<= 1) {
        for (unsigned j = k >> 1; j > 0; j >>= 1) {
            __syncthreads();
#pragma unroll
            for (int rr = 0; rr < 4; rr++) {
                unsigned tt = t + rr * 1024;
                unsigned ixj = tt ^ j;
                if (ixj > tt) {
                    unsigned long long a = s[tt], bb = s[ixj];
                    bool desc = ((tt & k) == 0);
                    if (desc ? (a < bb) : (a > bb)) { s[tt] = bb; s[ixj] = a; }
                }
            }
        }
    }
    __syncthreads();
    g_sel[b][t] = s[t];
}

// ---------------- K6: decode boxes for selected 4096 points --------------
__global__ void __launch_bounds__(128) k_decode(
        const float* __restrict__ feat,
        const int*   __restrict__ coor,
        const float* __restrict__ Wr,
        const float* __restrict__ br,
        int N) {
    __shared__ float sW[256 * 9];
    __shared__ float srow[4][256];
    for (int i = threadIdx.x; i < 256 * 9; i += 128) sW[i] = Wr[i];
    __syncthreads();

    const int b = blockIdx.y;
    const int warp = threadIdx.x >> 5;
    const int lane = threadIdx.x & 31;
    const int k = blockIdx.x * 4 + warp;

    unsigned long long key = g_sel[b][k];
    unsigned idx = ~(unsigned)(key & 0xffffffffu);
    bool valid = (idx < (unsigned)N);
    if (!valid) idx = 0;

    {
        const float4* f4 = (const float4*)(feat + (size_t)idx * 256);
        float4 a = f4[lane * 2 + 0];
        float4 c4 = f4[lane * 2 + 1];
        ((float4*)srow[warp])[lane * 2 + 0] = a;
        ((float4*)srow[warp])[lane * 2 + 1] = c4;
    }
    __syncwarp();

    float acc = 0.0f;
    if (lane < 8) {
        const float* row = srow[warp];
#pragma unroll 8
        for (int kk = 0; kk < 256; kk++) {
            acc = __fmaf_rn(row[kk], sW[kk * 9 + lane], acc);
        }
        acc = __fadd_rn(acc, br[lane]);
    }

    float r[8];
#pragma unroll
    for (int j = 0; j < 8; j++) r[j] = __shfl_sync(0xffffffffu, acc, j);

    if (lane == 0) {
        float out[8];
        if (valid) {
            float cx = __fmul_rn((float)coor[(size_t)idx * 2 + 0], 0.8f);
            float cy = __fmul_rn((float)coor[(size_t)idx * 2 + 1], 0.8f);
            out[0] = __fadd_rn(cx, r[0]);
            out[1] = __fadd_rn(cy, r[1]);
            out[2] = r[2];
            out[3] = exp_cr(fminf(fmaxf(r[3], -6.0f), 6.0f));
            out[4] = exp_cr(fminf(fmaxf(r[4], -6.0f), 6.0f));
            out[5] = exp_cr(fminf(fmaxf(r[5], -6.0f), 6.0f));
            out[6] = atan2_cr(r[6], r[7]);
            out[7] = __uint_as_float((unsigned)(key >> 32));
        } else {
#pragma unroll
            for (int j = 0; j < 8; j++) out[j] = 0.0f;
        }
#pragma unroll
        for (int j = 0; j < 8; j++) g_boxes[b][k][j] = out[j];
    }
}

// ---------------- K7: IoU suppression bitmask (parallel) ------------------
__global__ void k_mask() {
    const int b = blockIdx.y;
    const int j = threadIdx.x;                 // column
    __shared__ float sx1[PRE], sx2[PRE], sy1[PRE], sy2[PRE], sa[PRE];

    float x = g_boxes[b][j][0], y = g_boxes[b][j][1];
    float l = g_boxes[b][j][3], w = g_boxes[b][j][4];
    bool jv = (~(unsigned)(g_sel[b][j] & 0xffffffffu)) < 0x7fffffffu;
    if (jv) {
        float lh = __fmul_rn(l, 0.5f);
        float wh = __fmul_rn(w, 0.5f);
        sx1[j] = __fadd_rn(x, -lh); sx2[j] = __fadd_rn(x, lh);
        sy1[j] = __fadd_rn(y, -wh); sy2[j] = __fadd_rn(y, wh);
        sa[j]  = __fmul_rn(l, w);
    } else {
        sx1[j] = 1e30f; sx2[j] = -1e30f;
        sy1[j] = 1e30f; sy2[j] = -1e30f;
        sa[j]  = 0.0f;
    }
    __syncthreads();

    const int i0 = blockIdx.x * 32;
    const float X1 = sx1[j], X2 = sx2[j], Y1 = sy1[j], Y2 = sy2[j], A = sa[j];
    for (int ii = 0; ii < 32; ii++) {
        int i = i0 + ii;
        float ix = fmaxf(__fadd_rn(fminf(sx2[i], X2), -fmaxf(sx1[i], X1)), 0.0f);
        float iy = fmaxf(__fadd_rn(fminf(sy2[i], Y2), -fmaxf(sy1[i], Y1)), 0.0f);
        float inter = __fmul_rn(ix, iy);
        float uni = __fadd_rn(__fadd_rn(sa[i], A), -inter);
        float iou = __fdiv_rn(inter, fmaxf(uni, 1e-6f));
        bool s = (j > i) && (iou > 0.1f);
        unsigned bal = __ballot_sync(0xffffffffu, s);
        if ((j & 31) == 0) {
            g_mask[b][i][j >> 5] = bal;
            if (bal) atomicOr(&g_rowflag[b][i >> 5], 1u << (i & 31));
        }
    }
}

// ---------------- K8: serial greedy scan (sparse rows only) + outputs -----
__global__ void k_scan_out(float* __restrict__ dout, int out_size) {
    const int b = blockIdx.x;
    const int t = threadIdx.x;
    __shared__ unsigned srem[32];

    if (t < 32) {
        unsigned rem = 0;
        unsigned flags = g_rowflag[b][t];
        for (int w = 0; w < 32; w++) {
            unsigned fw = __shfl_sync(0xffffffffu, flags, w);
            while (fw) {
                int bp = __ffs(fw) - 1;
                fw &= fw - 1;
                int i = w * 32 + bp;
                unsigned owner = __shfl_sync(0xffffffffu, rem, i >> 5);
                if (!((owner >> (i & 31)) & 1u)) {
                    rem |= g_mask[b][i][t];
                }
            }
        }
        srem[t] = rem;
    }
    __syncthreads();

    bool jv = (~(unsigned)(g_sel[b][t] & 0xffffffffu)) < 0x7fffffffu;
    bool keep = jv && !((srem[t >> 5] >> (t & 31)) & 1u);
    float kf = keep ? 1.0f : 0.0f;

    int obase = (b * PRE + t) * 8;
#pragma unroll
    for (int c = 0; c < 8; c++) {
        if (obase + c < out_size) dout[obase + c] = g_boxes[b][t][c] * kf;
    }
    int lbpos = NUMB * PRE * 8 + b * PRE + t;          // label section (always 0)
    if (lbpos < out_size) dout[lbpos] = 0.0f;
    int kppos = NUMB * PRE * 9 + b * PRE + t;          // keep section
    if (kppos < out_size) dout[kppos] = kf;
}

// ---------------- launcher ----------------
extern "C" void kernel_launch(void* const* d_in, const int* in_sizes, int n_in,
                              void* d_out, int out_size) {
    const float* feat  = (const float*)d_in[0];
    const int*   bidx  = (const int*)d_in[1];
    const int*   coor  = (const int*)d_in[2];
    const float* Wc    = (const float*)d_in[3];
    const float* bc    = (const float*)d_in[4];
    const float* Wr    = (const float*)d_in[5];
    const float* br    = (const float*)d_in[6];
    float* out = (float*)d_out;

    const int N = in_sizes[1];

    k_init<<<(NUMB * HBINS) / 256, 256>>>();
    k_score<<<(N + 255) / 256, 256>>>(feat, bidx, Wc, bc, Wr, br, N);
    k_thresh<<<NUMB, 1024>>>();
    k_compact<<<(N + 255) / 256, 256>>>(bidx, N);
    k_rescore<<<dim3(CAND / 4, NUMB), 128>>>(feat, Wc, bc, Wr, br, N);
    k_rank<<<NUMB, 1024>>>();
    k_decode<<<dim3(PRE / 4, NUMB), 128>>>(feat, coor, Wr, br, N);
    k_mask<<<dim3(PRE / 32, NUMB), 1024>>>();
    k_scan_out<<<NUMB, 1024>>>(out, out_size);
}